// round 4
// baseline (speedup 1.0000x reference)
#include <cuda_runtime.h>
#include <math.h>

// ---------------------------------------------------------------------------
// Focal_loss2: fused focal-loss (neg maxpool-masked branch + pos gather branch)
//
// Inputs (metadata order):
//  0 logits_a  f32 [2,2,128,128,128]
//  1 logits_b  f32 [2,2,64,64,64]
//  2 prob_a    f32 [2,2,128,128,128]
//  3 prob_b    f32 [2,2,64,64,64]
//  4 connects_a i32 same shape as logits_a
//  5 connects_b i32 same shape as logits_b
//  6 coord_a   i32 [2,64,4]
//  7 coord_b   i32 [2,64,4]
//  8 fnames    f32 [2]   (unused by outputs)
//
// Output (f32, 38 elems): [loss_pos, loss_neg, count_pos, count_neg,
//                          wsum_pos, wsum_neg, pred_prob_min[2,2,8]]
// ---------------------------------------------------------------------------

#define TX 32
#define TY 8
#define ZCHUNK 32
#define NTHREADS (TX*TY)

// Global accumulators (no allocation allowed -> __device__ globals)
__device__ double g_neg[2][2];   // [level][{sum(nll*w), sum(w)}]
__device__ double g_pos[2][2];   // [level][{sum(loss terms), sum(w1*valid)}]
__device__ int    g_segmin[32];  // [level][B][T_TAGS] as int-ordered floats

__device__ __forceinline__ float softplusf(float x) {
    // log(1 + exp(x)), overflow-safe
    return fmaxf(x, 0.f) + log1pf(expf(-fabsf(x)));
}

__global__ void init_kernel() {
    int t = threadIdx.x;
    if (t < 4) {
        g_neg[t >> 1][t & 1] = 0.0;
        g_pos[t >> 1][t & 1] = 0.0;
    }
    if (t < 32) g_segmin[t] = 0x7F800000; // +inf
}

// -------------------- negative branch: fused sigmoid/softplus + 3^3 maxpool mask
// Grid: (xt*yt, D/ZCHUNK, B*A). Block: (TX, TY).
// z-marching with a 3-plane shared ring; per-plane 3x3 max held in registers.
__global__ __launch_bounds__(NTHREADS)
void neg_kernel(const float* __restrict__ logits,
                const float* __restrict__ prob,
                int D, int xt, int lvl)
{
    __shared__ float sh[3][TY + 2][TX + 2];

    const int bx = blockIdx.x % xt;
    const int by = blockIdx.x / xt;
    const int z0 = blockIdx.y * ZCHUNK;
    const size_t vol = (size_t)D * D * D;
    const float* L = logits + (size_t)blockIdx.z * vol;
    const float* P = prob   + (size_t)blockIdx.z * vol;

    const int tx = threadIdx.x, ty = threadIdx.y;
    const int tid = ty * TX + tx;
    const int gx0 = bx * TX - 1, gy0 = by * TY - 1;

    auto loadPlane = [&](int z, int slot) {
        const bool zin = ((unsigned)z < (unsigned)D);
        float* dst = &sh[slot][0][0];
        for (int i = tid; i < (TY + 2) * (TX + 2); i += NTHREADS) {
            int r = i / (TX + 2);
            int c = i - r * (TX + 2);
            int gy = gy0 + r, gx = gx0 + c;
            float v = -INFINITY;
            if (zin && (unsigned)gy < (unsigned)D && (unsigned)gx < (unsigned)D)
                v = L[((size_t)z * D + gy) * D + gx];
            dst[i] = v;
        }
    };

    auto plane3x3 = [&](int slot, float& cen) -> float {
        float m = -INFINITY;
        #pragma unroll
        for (int r = 0; r < 3; r++) {
            #pragma unroll
            for (int c = 0; c < 3; c++) {
                float v = sh[slot][ty + r][tx + c];
                if (r == 1 && c == 1) cen = v;
                m = fmaxf(m, v);
            }
        }
        return m;
    };

    // Prologue: planes z0-1 and z0
    loadPlane(z0 - 1, 0);
    loadPlane(z0,     1);
    __syncthreads();

    float cen, cdummy;
    float mprev = plane3x3(0, cdummy);
    float mcur  = plane3x3(1, cen);

    float s_lw = 0.f, s_w = 0.f;
    const int gy = by * TY + ty, gx = bx * TX + tx;

    for (int zi = 0; zi < ZCHUNK; ++zi) {
        const int z = z0 + zi;
        const int slot = (zi + 2) % 3;
        loadPlane(z + 1, slot);     // overwrites plane z-2 (last read 3 iters ago)
        __syncthreads();            // single barrier per iteration is sufficient

        float cen_next;
        const float mnext = plane3x3(slot, cen_next);
        const float M = fmaxf(mprev, fmaxf(mcur, mnext));

        const float pg = P[((size_t)z * D + gy) * D + gx];
        // max_filter (monotone sigmoid => compare logits) AND negmask
        if (M == cen && pg == -1.0f) {
            const float s = 1.f / (1.f + expf(-cen));
            const float w = s * s;              // stop_grad(prob)^ALPHA, ALPHA=2
            s_w  += w;
            s_lw += w * softplusf(cen);         // nll = -log(1-sigmoid) = softplus
        }
        mprev = mcur; mcur = mnext; cen = cen_next;
    }

    // Block reduction -> double atomics
    #pragma unroll
    for (int o = 16; o; o >>= 1) {
        s_lw += __shfl_down_sync(0xFFFFFFFFu, s_lw, o);
        s_w  += __shfl_down_sync(0xFFFFFFFFu, s_w,  o);
    }
    __shared__ float red[2][TY];
    if (tx == 0) { red[0][ty] = s_lw; red[1][ty] = s_w; }
    __syncthreads();
    if (tid == 0) {
        float tlw = 0.f, tw = 0.f;
        #pragma unroll
        for (int i = 0; i < TY; i++) { tlw += red[0][i]; tw += red[1][i]; }
        atomicAdd(&g_neg[lvl][0], (double)tlw);
        atomicAdd(&g_neg[lvl][1], (double)tw);
    }
}

// -------------------- positive branch + segment-min (tiny: 2 blocks x 128 thr)
__global__ void pos_kernel(const float* __restrict__ logitsA,
                           const int* __restrict__ connA,
                           const int* __restrict__ coordA,
                           const float* __restrict__ logitsB,
                           const int* __restrict__ connB,
                           const int* __restrict__ coordB)
{
    const int lvl = blockIdx.x;
    const float* L  = lvl ? logitsB : logitsA;
    const int*   C  = lvl ? connB   : connA;
    const int*   CO = lvl ? coordB  : coordA;
    const int    D  = lvl ? 64 : 128;

    const int t = threadIdx.x;           // 0..127  (= B*M)
    const int b = t >> 6, m = t & 63;
    const int* row = CO + ((size_t)(b * 64 + m)) * 4;
    int c0 = row[0], c1 = row[1], c2 = row[2], c3 = row[3];
    const bool valid = (c0 > -1);
    if (!valid) { c0 = c1 = c2 = c3 = 0; }

    const size_t idx = ((((size_t)(b * 2 + c0) * D + c1) * D + c2) * D + c3);
    const float lp = L[idx];
    const float pp = 1.f / (1.f + expf(-lp));
    const float om = 1.f - pp;
    const float w1 = om * om;

    // w2 = ANCHOR_POS_FACTOR[c0] == 1.0 always
    float loss = valid ? softplusf(-lp) * w1 : 0.f;   // -log_sigmoid(lp)*w1
    float w1v  = valid ? w1 : 0.f;

    if (valid) {
        const int tag = C[idx];                       // 0..7
        atomicMin(&g_segmin[lvl * 16 + b * 8 + tag], __float_as_int(w1));
    }

    #pragma unroll
    for (int o = 16; o; o >>= 1) {
        loss += __shfl_down_sync(0xFFFFFFFFu, loss, o);
        w1v  += __shfl_down_sync(0xFFFFFFFFu, w1v,  o);
    }
    __shared__ float red[2][4];
    const int lane = t & 31, wid = t >> 5;
    if (lane == 0) { red[0][wid] = loss; red[1][wid] = w1v; }
    __syncthreads();
    if (t == 0) {
        g_pos[lvl][0] = (double)(red[0][0] + red[0][1] + red[0][2] + red[0][3]);
        g_pos[lvl][1] = (double)(red[1][0] + red[1][1] + red[1][2] + red[1][3]);
    }
}

// -------------------- finalize: apply level factors, write 38 outputs
__global__ void fin_kernel(float* __restrict__ out)
{
    const int t = threadIdx.x;
    if (t == 0) {
        const double fa = 2.0, fb = 1.0;   // POS_FACTOR == NEG_FACTOR == [2,1]
        out[0] = (float)(g_pos[0][0] * fa + g_pos[1][0] * fb);  // cls_loss_pos
        out[1] = (float)(g_neg[0][0] * fa + g_neg[1][0] * fb);  // cls_loss_neg
        out[2] = (float)(g_pos[0][1]      + g_pos[1][1]);       // count_pos
        out[3] = (float)(g_neg[0][1]      + g_neg[1][1]);       // count_neg
        out[4] = (float)(g_pos[0][1] * fa + g_pos[1][1] * fb);  // wsum_pos
        out[5] = (float)(g_neg[0][1] * fa + g_neg[1][1] * fb);  // wsum_neg
    }
    if (t < 32) {
        const int bits = g_segmin[t];
        out[6 + t] = (bits == 0x7F800000) ? -1.0f : __int_as_float(bits);
    }
}

extern "C" void kernel_launch(void* const* d_in, const int* in_sizes, int n_in,
                              void* d_out, int out_size)
{
    (void)in_sizes; (void)n_in; (void)out_size;
    const float* logits_a = (const float*)d_in[0];
    const float* logits_b = (const float*)d_in[1];
    const float* prob_a   = (const float*)d_in[2];
    const float* prob_b   = (const float*)d_in[3];
    const int*   conn_a   = (const int*)d_in[4];
    const int*   conn_b   = (const int*)d_in[5];
    const int*   coord_a  = (const int*)d_in[6];
    const int*   coord_b  = (const int*)d_in[7];
    float* out = (float*)d_out;

    init_kernel<<<1, 64>>>();

    {   // level a: D=128
        const int D = 128, xt = D / TX, yt = D / TY;
        dim3 grid(xt * yt, D / ZCHUNK, 4);
        neg_kernel<<<grid, dim3(TX, TY)>>>(logits_a, prob_a, D, xt, 0);
    }
    {   // level b: D=64
        const int D = 64, xt = D / TX, yt = D / TY;
        dim3 grid(xt * yt, D / ZCHUNK, 4);
        neg_kernel<<<grid, dim3(TX, TY)>>>(logits_b, prob_b, D, xt, 1);
    }
    pos_kernel<<<2, 128>>>(logits_a, conn_a, coord_a, logits_b, conn_b, coord_b);
    fin_kernel<<<1, 64>>>(out);
}

// round 6
// speedup vs baseline: 1.7285x; 1.7285x over previous
#include <cuda_runtime.h>
#include <math.h>

#define FULLMASK 0xFFFFFFFFu

// ---------------------------------------------------------------------------
// Focal_loss2 — fused focal loss.
// Inputs: logits_a f32[2,2,128^3], logits_b f32[2,2,64^3], prob_a, prob_b,
//         connects_a i32, connects_b i32, coord_a i32[2,64,4], coord_b, fnames.
// Output f32[38]: [loss_pos, loss_neg, count_pos, count_neg, wsum_pos,
//                  wsum_neg, pred_prob_min[2,2,8]]
// ---------------------------------------------------------------------------

constexpr int ZC   = 32;                  // z-march chunk
constexpr int A_YT = 22, A_ZT = 4;        // D=128: y tiles (OUT=6), z chunks
constexpr int B_YT = 5,  B_ZT = 2;        // D=64 : y tiles (OUT=14), z chunks
constexpr int NBLK_A = A_YT * A_ZT * 4;   // 352
constexpr int NBLK_B = B_YT * B_ZT * 4;   // 40
constexpr int NBLK   = NBLK_A + NBLK_B;   // 392
constexpr int PLANE  = 256;               // float4 entries per z-plane (= threads)

// per-block negative-branch partials: {sum(w*nll), sum(w)} — every slot is
// written each launch, so no init kernel / atomics are needed.
__device__ float2 g_part[NBLK];

__device__ __forceinline__ float softplusf_(float x) {
    return fmaxf(x, 0.f) + log1pf(__expf(-fabsf(x)));
}

// ---------------------------------------------------------------------------
// Negative branch: fused 3x3x3 local-max mask + focal weighting.
// Block = 256 threads. LPR = D/4 lanes per x-row, ROWS = 256/LPR y-rows
// (OUT = ROWS-2 output rows), marching z with a 3-plane smem ring of
// x-maxed rows + raw rows. Depth-2 register prefetch of z-planes.
// ---------------------------------------------------------------------------
template<int D, int YT, int ZT>
__device__ __forceinline__ void neg_impl(const float* __restrict__ L,
                                         const float* __restrict__ P,
                                         int bid, int gbid,
                                         float4* sxm, float4* sraw, float* sred)
{
    constexpr int LPR  = D / 4;
    constexpr int ROWS = 256 / LPR;
    constexpr int OUT  = ROWS - 2;

    const int ytile = bid % YT;
    const int zc    = (bid / YT) % ZT;
    const int ba    = bid / (YT * ZT);

    const int tid = threadIdx.x;
    const int r   = tid / LPR;            // row within block (0..ROWS-1)
    const int xl  = tid % LPR;            // x lane
    const int x   = xl * 4;
    const int y0  = ytile * OUT;          // first output row
    const int z0  = zc * ZC;
    const int gy  = y0 - 1 + r;           // loaded row (with halo)
    const bool yin = (unsigned)gy < (unsigned)D;

    const size_t vol = (size_t)D * D * D;
    const float* Lb = L + (size_t)ba * vol;
    const float* Pb = P + (size_t)ba * vol;
    const long long rowoff = (long long)gy * D + x;

    auto loadPlane = [&](int z) -> float4 {
        float4 v = make_float4(-INFINITY, -INFINITY, -INFINITY, -INFINITY);
        if (yin && (unsigned)z < (unsigned)D)
            v = *reinterpret_cast<const float4*>(Lb + rowoff + (long long)z * D * D);
        return v;
    };

    // x-direction 3-max per component; neighbors across lanes via shuffle.
    auto xmax3 = [&](float4 v) -> float4 {
        float lft = __shfl_up_sync(FULLMASK, v.w, 1);
        float rgt = __shfl_down_sync(FULLMASK, v.x, 1);
        if (xl == 0)       lft = -INFINITY;   // x==0 edge (also fixes row wrap in-warp)
        if (xl == LPR - 1) rgt = -INFINITY;   // x==D-4 edge
        float4 m;
        m.x = fmaxf(lft,  fmaxf(v.x, v.y));
        m.y = fmaxf(v.x,  fmaxf(v.y, v.z));
        m.z = fmaxf(v.y,  fmaxf(v.z, v.w));
        m.w = fmaxf(rgt,  fmaxf(v.z, v.w));
        return m;
    };

    auto st = [&](int slot, float4 v, bool withRaw) {
        sxm[slot * PLANE + r * LPR + xl] = xmax3(v);
        if (withRaw) sraw[slot * PLANE + r * LPR + xl] = v;
    };

    // y-direction 3-max of x-maxed rows (rows r, r+1, r+2 of a plane);
    // only called by comp threads (r <= ROWS-3), so r+2 stays in-plane.
    auto pm3 = [&](int slot) -> float4 {
        float4 a = sxm[slot * PLANE + r * LPR + xl];
        float4 b = sxm[slot * PLANE + (r + 1) * LPR + xl];
        float4 c = sxm[slot * PLANE + (r + 2) * LPR + xl];
        float4 m;
        m.x = fmaxf(a.x, fmaxf(b.x, c.x));
        m.y = fmaxf(a.y, fmaxf(b.y, c.y));
        m.z = fmaxf(a.z, fmaxf(b.z, c.z));
        m.w = fmaxf(a.w, fmaxf(b.w, c.w));
        return m;
    };

    const int  gyo  = y0 + r;                                   // output row
    const bool comp = (r < OUT) && ((unsigned)gyo < (unsigned)D);
    const float* pp = Pb + ((size_t)(comp ? gyo : 0) * D + x);

    // ---- prologue: plane z0-1 (xm only) and z0; start depth-2 prefetch
    {
        float4 v = loadPlane(z0 - 1);
        st(0, v, false);
    }
    float4 q0 = loadPlane(z0);
    float4 q1 = loadPlane(z0 + 1);
    __syncthreads();
    float4 pm_prev = make_float4(-INFINITY, -INFINITY, -INFINITY, -INFINITY);
    if (comp) pm_prev = pm3(0);
    st(1, q0, true);
    q0 = q1;
    q1 = loadPlane(z0 + 2);
    __syncthreads();
    float4 pm_cur = make_float4(-INFINITY, -INFINITY, -INFINITY, -INFINITY);
    float4 cen    = make_float4(0.f, 0.f, 0.f, 0.f);
    if (comp) {
        pm_cur = pm3(1);
        cen    = sraw[1 * PLANE + (r + 1) * LPR + xl];
    }

    float s_lw = 0.f, s_w = 0.f;

    // ---- main z loop: one barrier per plane; ring of 3 makes it sufficient
    for (int i = 0; i < ZC; ++i) {
        const int zout = z0 + i;
        const int snew = (i + 2) % 3;
        st(snew, q0, true);                       // plane zout+1
        q0 = q1;
        if (i + 3 <= ZC) q1 = loadPlane(z0 + i + 3);   // prefetch 2 ahead
        __syncthreads();
        if (comp) {
            float4 pm_next = pm3(snew);
            float4 M;
            M.x = fmaxf(pm_prev.x, fmaxf(pm_cur.x, pm_next.x));
            M.y = fmaxf(pm_prev.y, fmaxf(pm_cur.y, pm_next.y));
            M.z = fmaxf(pm_prev.z, fmaxf(pm_cur.z, pm_next.z));
            M.w = fmaxf(pm_prev.w, fmaxf(pm_cur.w, pm_next.w));
            const bool m0 = (M.x == cen.x), m1 = (M.y == cen.y);
            const bool m2 = (M.z == cen.z), m3 = (M.w == cen.w);
            if (m0 | m1 | m2 | m3) {              // ~15% of float4s: load prob only then
                const float4 pg = *reinterpret_cast<const float4*>(pp + (size_t)zout * D * D);
                if (m0 && pg.x == -1.0f) {
                    float e = __expf(-cen.x); float s = 1.0f / (1.0f + e);
                    float w = s * s; s_w += w; s_lw += w * softplusf_(cen.x);
                }
                if (m1 && pg.y == -1.0f) {
                    float e = __expf(-cen.y); float s = 1.0f / (1.0f + e);
                    float w = s * s; s_w += w; s_lw += w * softplusf_(cen.y);
                }
                if (m2 && pg.z == -1.0f) {
                    float e = __expf(-cen.z); float s = 1.0f / (1.0f + e);
                    float w = s * s; s_w += w; s_lw += w * softplusf_(cen.z);
                }
                if (m3 && pg.w == -1.0f) {
                    float e = __expf(-cen.w); float s = 1.0f / (1.0f + e);
                    float w = s * s; s_w += w; s_lw += w * softplusf_(cen.w);
                }
            }
            pm_prev = pm_cur; pm_cur = pm_next;
            cen = sraw[snew * PLANE + (r + 1) * LPR + xl];   // raw center of next zout
        }
    }

    // ---- block reduction -> per-block partial
    #pragma unroll
    for (int o = 16; o; o >>= 1) {
        s_lw += __shfl_down_sync(FULLMASK, s_lw, o);
        s_w  += __shfl_down_sync(FULLMASK, s_w,  o);
    }
    const int lane = tid & 31, w = tid >> 5;
    __syncthreads();
    if (lane == 0) { sred[w] = s_lw; sred[8 + w] = s_w; }
    __syncthreads();
    if (tid == 0) {
        float a = 0.f, b = 0.f;
        #pragma unroll
        for (int i = 0; i < 8; i++) { a += sred[i]; b += sred[8 + i]; }
        g_part[gbid] = make_float2(a, b);
    }
}

__global__ __launch_bounds__(256)
void neg_all_kernel(const float* __restrict__ La, const float* __restrict__ Pa,
                    const float* __restrict__ Lb, const float* __restrict__ Pb)
{
    __shared__ float4 sxm[3 * PLANE];
    __shared__ float4 sraw[3 * PLANE];
    __shared__ float  sred[16];
    const int bid = blockIdx.x;
    if (bid < NBLK_A) neg_impl<128, A_YT, A_ZT>(La, Pa, bid, bid, sxm, sraw, sred);
    else              neg_impl<64,  B_YT, B_ZT>(Lb, Pb, bid - NBLK_A, bid, sxm, sraw, sred);
}

// ---------------------------------------------------------------------------
// Positive branch + segment-min + finalize, single block of 256 threads.
// Threads 0-127: level a (B*M = 128), threads 128-255: level b.
// ---------------------------------------------------------------------------
__global__ void posfin_kernel(const float* __restrict__ La, const int* __restrict__ Ca,
                              const int* __restrict__ coA,
                              const float* __restrict__ Lb, const int* __restrict__ Cb,
                              const int* __restrict__ coB,
                              float* __restrict__ out)
{
    __shared__ int    ssegmin[32];
    __shared__ float  sp[2][2][4];       // [lvl][{loss,w}][warp-in-half]
    __shared__ double sn[4][8];          // neg partial reduce
    const int t = threadIdx.x;
    if (t < 32) ssegmin[t] = 0x7F800000; // +inf

    // ---- negative partial sums (double)
    double nl0 = 0, nw0 = 0, nl1 = 0, nw1 = 0;
    for (int i = t; i < NBLK; i += 256) {
        float2 p = g_part[i];
        if (i < NBLK_A) { nl0 += p.x; nw0 += p.y; }
        else            { nl1 += p.x; nw1 += p.y; }
    }

    // ---- positive branch
    const int lvl = t >> 7, u = t & 127;
    const int b = u >> 6, m = u & 63;
    const float* L  = lvl ? Lb  : La;
    const int*   C  = lvl ? Cb  : Ca;
    const int*   CO = lvl ? coB : coA;
    const int    D  = lvl ? 64  : 128;

    const int* row = CO + (size_t)(b * 64 + m) * 4;
    int c0 = row[0], c1 = row[1], c2 = row[2], c3 = row[3];
    const bool valid = (c0 > -1);
    if (!valid) { c0 = c1 = c2 = c3 = 0; }
    const size_t idx = ((((size_t)(b * 2 + c0) * D + c1) * D + c2) * D + c3);
    const float lp = L[idx];
    const float s  = 1.0f / (1.0f + __expf(-lp));
    const float om = 1.0f - s;
    const float w1 = om * om;
    float loss = valid ? softplusf_(-lp) * w1 : 0.f;   // -log_sigmoid(lp)*w1 (w2==1)
    float w1v  = valid ? w1 : 0.f;

    __syncthreads();                                   // ssegmin init visible
    if (valid) {
        const int tag = C[idx];
        atomicMin(&ssegmin[lvl * 16 + b * 8 + tag], __float_as_int(w1));
    }

    // warp reductions
    #pragma unroll
    for (int o = 16; o; o >>= 1) {
        loss += __shfl_down_sync(FULLMASK, loss, o);
        w1v  += __shfl_down_sync(FULLMASK, w1v,  o);
        nl0  += __shfl_down_sync(FULLMASK, nl0, o);
        nw0  += __shfl_down_sync(FULLMASK, nw0, o);
        nl1  += __shfl_down_sync(FULLMASK, nl1, o);
        nw1  += __shfl_down_sync(FULLMASK, nw1, o);
    }
    const int lane = t & 31, wi = t >> 5;
    if (lane == 0) {
        sp[lvl][0][wi & 3] = loss;
        sp[lvl][1][wi & 3] = w1v;
        sn[0][wi] = nl0; sn[1][wi] = nw0; sn[2][wi] = nl1; sn[3][wi] = nw1;
    }
    __syncthreads();

    if (t == 0) {
        double pl0 = 0, pw0 = 0, pl1 = 0, pw1 = 0;
        #pragma unroll
        for (int i = 0; i < 4; i++) {
            pl0 += sp[0][0][i]; pw0 += sp[0][1][i];
            pl1 += sp[1][0][i]; pw1 += sp[1][1][i];
        }
        double NL0 = 0, NW0 = 0, NL1 = 0, NW1 = 0;
        #pragma unroll
        for (int i = 0; i < 8; i++) {
            NL0 += sn[0][i]; NW0 += sn[1][i]; NL1 += sn[2][i]; NW1 += sn[3][i];
        }
        // POS_FACTOR == NEG_FACTOR == [2, 1]
        out[0] = (float)(pl0 * 2.0 + pl1);   // cls_loss_pos
        out[1] = (float)(NL0 * 2.0 + NL1);   // cls_loss_neg
        out[2] = (float)(pw0       + pw1);   // count_pos
        out[3] = (float)(NW0       + NW1);   // count_neg
        out[4] = (float)(pw0 * 2.0 + pw1);   // wsum_pos
        out[5] = (float)(NW0 * 2.0 + NW1);   // wsum_neg
    }
    if (t < 32) {
        const int bits = ssegmin[t];
        out[6 + t] = (bits == 0x7F800000) ? -1.0f : __int_as_float(bits);
    }
}

extern "C" void kernel_launch(void* const* d_in, const int* in_sizes, int n_in,
                              void* d_out, int out_size)
{
    (void)in_sizes; (void)n_in; (void)out_size;
    const float* logits_a = (const float*)d_in[0];
    const float* logits_b = (const float*)d_in[1];
    const float* prob_a   = (const float*)d_in[2];
    const float* prob_b   = (const float*)d_in[3];
    const int*   conn_a   = (const int*)d_in[4];
    const int*   conn_b   = (const int*)d_in[5];
    const int*   coord_a  = (const int*)d_in[6];
    const int*   coord_b  = (const int*)d_in[7];
    float* out = (float*)d_out;

    neg_all_kernel<<<NBLK, 256>>>(logits_a, prob_a, logits_b, prob_b);
    posfin_kernel<<<1, 256>>>(logits_a, conn_a, coord_a,
                              logits_b, conn_b, coord_b, out);
}